// round 8
// baseline (speedup 1.0000x reference)
#include <cuda_runtime.h>

#define NGROUPS 8
#define THREADS 256
#define NBLOCKS 888                   // 6 CTAs/SM * 148 SMs (persistent)
#define MAX_BLOCKS 2048
#define FLUSH_EVERY 63                // packed 8-bit counts: flush before overflow

// Scratch (no allocations allowed). g_part fully overwritten each run;
// g_counter reset to 0 by the last block (deterministic across replays).
__device__ float    g_part[MAX_BLOCKS * 2 * NGROUPS];
__device__ unsigned g_counter = 0;

__device__ __forceinline__ void block_reduce_16(float* s, float* c,
                                                float* red /* [THREADS/32][16] */) {
#pragma unroll
    for (int j = 0; j < NGROUPS; j++) {
#pragma unroll
        for (int o = 16; o > 0; o >>= 1) {
            s[j] += __shfl_down_sync(0xffffffffu, s[j], o);
            c[j] += __shfl_down_sync(0xffffffffu, c[j], o);
        }
    }
    int lane = threadIdx.x & 31;
    int warp = threadIdx.x >> 5;
    if (lane == 0) {
#pragma unroll
        for (int j = 0; j < NGROUPS; j++) {
            red[warp * 16 + j]           = s[j];
            red[warp * 16 + NGROUPS + j] = c[j];
        }
    }
    __syncthreads();
    if (threadIdx.x < 2 * NGROUPS) {
        float t = 0.0f;
#pragma unroll
        for (int w = 0; w < THREADS / 32; w++) t += red[w * 16 + threadIdx.x];
        red[threadIdx.x] = t;   // result lives in red[0..15]
    }
    __syncthreads();
}

__global__ __launch_bounds__(THREADS, 6) void fused_kernel(
    const float* __restrict__ in, const int* __restrict__ tgt,
    const int* __restrict__ grp, float* __restrict__ out, int n)
{
    __shared__ float red[(THREADS / 32) * 16];
    __shared__ bool  is_last;

    float s[NGROUPS], c[NGROUPS];
#pragma unroll
    for (int j = 0; j < NGROUPS; j++) { s[j] = 0.0f; c[j] = 0.0f; }

    int stride = gridDim.x * blockDim.x;
    int i0 = blockIdx.x * blockDim.x + threadIdx.x;

    int i = i0;
    while (i < n) {
        // Packed 8-bit counts for up to FLUSH_EVERY rows: groups 0-3 in
        // pk0 bytes, groups 4-7 in pk1 bytes. Saves 6 registers + 8 adds/row.
        unsigned pk0 = 0, pk1 = 0;
        int iters = 0;

#pragma unroll 2
        for (; i < n && iters < FLUSH_EVERY; i += stride, iters++) {
            // Whole-row load: all addresses depend only on i (no chained
            // gather). Warp covers 2048 contiguous bytes -> sequential DRAM.
            const float4* row = (const float4*)(in + ((size_t)i << 4));
            float4 r0 = __ldcs(row + 0);
            float4 r1 = __ldcs(row + 1);
            float4 r2 = __ldcs(row + 2);
            float4 r3 = __ldcs(row + 3);
            int t = __ldcs(tgt + i);
            int g = __ldcs(grp + i);

            // 16 -> 1 select tree
            float4 X = (t & 8) ? ((t & 4) ? r3 : r2) : ((t & 4) ? r1 : r0);
            float  v = (t & 2) ? ((t & 1) ? X.w : X.z)
                               : ((t & 1) ? X.y : X.x);

            float e = fabsf(1.0f - v);
#pragma unroll
            for (int j = 0; j < NGROUPS; j++)
                s[j] += (g == j) ? e : 0.0f;

            // count: one shifted add into packed bytes
            unsigned inc = 1u << ((g & 3) * 8);
            if (g & 4) pk1 += inc; else pk0 += inc;
        }

        // flush packed counts into float accumulators
#pragma unroll
        for (int j = 0; j < 4; j++) {
            c[j]     += (float)((pk0 >> (j * 8)) & 0xFFu);
            c[j + 4] += (float)((pk1 >> (j * 8)) & 0xFFu);
        }
    }

    block_reduce_16(s, c, red);

    if (threadIdx.x < 2 * NGROUPS)
        g_part[blockIdx.x * 2 * NGROUPS + threadIdx.x] = red[threadIdx.x];
    __syncthreads();

    if (threadIdx.x == 0) {
        __threadfence();
        unsigned v = atomicAdd(&g_counter, 1u);
        is_last = (v == gridDim.x - 1);
    }
    __syncthreads();
    if (!is_last) return;

    // Final reduction over per-block partials (L2-hot)
    float fs[NGROUPS], fc[NGROUPS];
#pragma unroll
    for (int j = 0; j < NGROUPS; j++) { fs[j] = 0.0f; fc[j] = 0.0f; }
    for (int b = threadIdx.x; b < gridDim.x; b += THREADS) {
#pragma unroll
        for (int j = 0; j < NGROUPS; j++) {
            fs[j] += g_part[b * 2 * NGROUPS + j];
            fc[j] += g_part[b * 2 * NGROUPS + NGROUPS + j];
        }
    }
    __syncthreads();
    block_reduce_16(fs, fc, red);

    if (threadIdx.x == 0) {
        float msum = 0.0f;
#pragma unroll
        for (int j = 0; j < NGROUPS; j++) {
            float cnt = red[NGROUPS + j];
            msum += (cnt > 0.0f) ? (red[j] / cnt) : 0.0f;
        }
        out[0] = fabsf(0.5f - msum * (1.0f / NGROUPS));
        g_counter = 0;   // reset for next graph replay
    }
}

extern "C" void kernel_launch(void* const* d_in, const int* in_sizes, int n_in,
                              void* d_out, int out_size) {
    const float* in  = (const float*)d_in[0];
    const int*   tgt = (const int*)d_in[1];
    const int*   grp = (const int*)d_in[2];
    float*       out = (float*)d_out;
    int n = in_sizes[1];  // N rows

    int blocks = NBLOCKS;
    int maxb = (n + THREADS - 1) / THREADS;
    if (blocks > maxb) blocks = maxb;
    if (blocks > MAX_BLOCKS) blocks = MAX_BLOCKS;
    if (blocks < 1) blocks = 1;
    fused_kernel<<<blocks, THREADS>>>(in, tgt, grp, out, n);
}

// round 9
// speedup vs baseline: 1.2220x; 1.2220x over previous
#include <cuda_runtime.h>

#define NGROUPS 8
#define THREADS 256
#define NBLOCKS 1024                  // exactly R1's geometry: 16 iters/thread
#define MAX_BLOCKS 2048

// Scratch (no allocations allowed). g_part fully overwritten each run;
// g_counter reset to 0 by the last block (deterministic across replays).
__device__ float    g_part[MAX_BLOCKS * 2 * NGROUPS];
__device__ unsigned g_counter = 0;

__device__ __forceinline__ void block_reduce_16(float* s, float* c,
                                                float* red /* [THREADS/32][16] */) {
#pragma unroll
    for (int j = 0; j < NGROUPS; j++) {
#pragma unroll
        for (int o = 16; o > 0; o >>= 1) {
            s[j] += __shfl_down_sync(0xffffffffu, s[j], o);
            c[j] += __shfl_down_sync(0xffffffffu, c[j], o);
        }
    }
    int lane = threadIdx.x & 31;
    int warp = threadIdx.x >> 5;
    if (lane == 0) {
#pragma unroll
        for (int j = 0; j < NGROUPS; j++) {
            red[warp * 16 + j]           = s[j];
            red[warp * 16 + NGROUPS + j] = c[j];
        }
    }
    __syncthreads();
    if (threadIdx.x < 2 * NGROUPS) {
        float t = 0.0f;
#pragma unroll
        for (int w = 0; w < THREADS / 32; w++) t += red[w * 16 + threadIdx.x];
        red[threadIdx.x] = t;   // result lives in red[0..15]
    }
    __syncthreads();
}

__global__ __launch_bounds__(THREADS) void fused_kernel(
    const float* __restrict__ in, const int* __restrict__ tgt,
    const int* __restrict__ grp, float* __restrict__ out, int n)
{
    __shared__ float red[(THREADS / 32) * 16];
    __shared__ bool  is_last;

    float s[NGROUPS], c[NGROUPS];
#pragma unroll
    for (int j = 0; j < NGROUPS; j++) { s[j] = 0.0f; c[j] = 0.0f; }

    int tid = blockIdx.x * blockDim.x + threadIdx.x;
    int total = gridDim.x * blockDim.x;

    // R1's rolling loop, verbatim: per-element load->gather->accumulate with
    // unroll 4. ptxas software-pipelines across iterations (next iteration's
    // index loads overlap this one's gather) — steady-state MLP beats every
    // hand-batched phase structure tried in R2-R8.
#pragma unroll 4
    for (int i = tid; i < n; i += total) {
        int t = __ldcs(tgt + i);
        int g = __ldcs(grp + i);
        float v = __ldcs(in + (size_t)i * 16 + t);
        float e = fabsf(1.0f - v);
#pragma unroll
        for (int j = 0; j < NGROUPS; j++) {
            bool m = (g == j);
            s[j] += m ? e : 0.0f;
            c[j] += m ? 1.0f : 0.0f;   // exact in f32 (< 2^24)
        }
    }

    block_reduce_16(s, c, red);

    if (threadIdx.x < 2 * NGROUPS)
        g_part[blockIdx.x * 2 * NGROUPS + threadIdx.x] = red[threadIdx.x];
    __syncthreads();

    if (threadIdx.x == 0) {
        __threadfence();
        unsigned v = atomicAdd(&g_counter, 1u);
        is_last = (v == gridDim.x - 1);
    }
    __syncthreads();
    if (!is_last) return;

    // Final reduction over per-block partials (L2-hot)
    float fs[NGROUPS], fc[NGROUPS];
#pragma unroll
    for (int j = 0; j < NGROUPS; j++) { fs[j] = 0.0f; fc[j] = 0.0f; }
    for (int b = threadIdx.x; b < gridDim.x; b += THREADS) {
#pragma unroll
        for (int j = 0; j < NGROUPS; j++) {
            fs[j] += g_part[b * 2 * NGROUPS + j];
            fc[j] += g_part[b * 2 * NGROUPS + NGROUPS + j];
        }
    }
    __syncthreads();
    block_reduce_16(fs, fc, red);

    if (threadIdx.x == 0) {
        float msum = 0.0f;
#pragma unroll
        for (int j = 0; j < NGROUPS; j++) {
            float cnt = red[NGROUPS + j];
            msum += (cnt > 0.0f) ? (red[j] / cnt) : 0.0f;
        }
        out[0] = fabsf(0.5f - msum * (1.0f / NGROUPS));
        g_counter = 0;   // reset for next graph replay
    }
}

extern "C" void kernel_launch(void* const* d_in, const int* in_sizes, int n_in,
                              void* d_out, int out_size) {
    const float* in  = (const float*)d_in[0];
    const int*   tgt = (const int*)d_in[1];
    const int*   grp = (const int*)d_in[2];
    float*       out = (float*)d_out;
    int n = in_sizes[1];  // N rows

    int blocks = NBLOCKS;
    int maxb = (n + THREADS - 1) / THREADS;
    if (blocks > maxb) blocks = maxb;
    if (blocks > MAX_BLOCKS) blocks = MAX_BLOCKS;
    if (blocks < 1) blocks = 1;
    fused_kernel<<<blocks, THREADS>>>(in, tgt, grp, out, n);
}

// round 10
// speedup vs baseline: 1.2606x; 1.0316x over previous
#include <cuda_runtime.h>

#define NGROUPS 8
#define THREADS 256
#define NBLOCKS 888                   // exactly 6 CTAs/SM * 148 SMs: ONE wave
#define MAX_BLOCKS 2048

// Scratch (no allocations allowed). g_part fully overwritten each run;
// g_counter reset to 0 by the last block (deterministic across replays).
__device__ float    g_part[MAX_BLOCKS * 2 * NGROUPS];
__device__ unsigned g_counter = 0;

__device__ __forceinline__ void block_reduce_16(float* s, float* c,
                                                float* red /* [THREADS/32][16] */) {
#pragma unroll
    for (int j = 0; j < NGROUPS; j++) {
#pragma unroll
        for (int o = 16; o > 0; o >>= 1) {
            s[j] += __shfl_down_sync(0xffffffffu, s[j], o);
            c[j] += __shfl_down_sync(0xffffffffu, c[j], o);
        }
    }
    int lane = threadIdx.x & 31;
    int warp = threadIdx.x >> 5;
    if (lane == 0) {
#pragma unroll
        for (int j = 0; j < NGROUPS; j++) {
            red[warp * 16 + j]           = s[j];
            red[warp * 16 + NGROUPS + j] = c[j];
        }
    }
    __syncthreads();
    if (threadIdx.x < 2 * NGROUPS) {
        float t = 0.0f;
#pragma unroll
        for (int w = 0; w < THREADS / 32; w++) t += red[w * 16 + threadIdx.x];
        red[threadIdx.x] = t;   // result lives in red[0..15]
    }
    __syncthreads();
}

__global__ __launch_bounds__(THREADS, 6) void fused_kernel(
    const float* __restrict__ in, const int* __restrict__ tgt,
    const int* __restrict__ grp, float* __restrict__ out, int n)
{
    __shared__ float red[(THREADS / 32) * 16];
    __shared__ bool  is_last;

    float s[NGROUPS], c[NGROUPS];
#pragma unroll
    for (int j = 0; j < NGROUPS; j++) { s[j] = 0.0f; c[j] = 0.0f; }

    int tid = blockIdx.x * blockDim.x + threadIdx.x;
    int total = gridDim.x * blockDim.x;

    // Proven rolling loop (R1/R9): per-element load->gather->accumulate,
    // unroll 4; ptxas software-pipelines across iterations for steady-state
    // MLP. Geometry change only: one full resident wave (888 CTAs, 6/SM).
#pragma unroll 4
    for (int i = tid; i < n; i += total) {
        int t = __ldcs(tgt + i);
        int g = __ldcs(grp + i);
        float v = __ldcs(in + (size_t)i * 16 + t);
        float e = fabsf(1.0f - v);
#pragma unroll
        for (int j = 0; j < NGROUPS; j++) {
            bool m = (g == j);
            s[j] += m ? e : 0.0f;
            c[j] += m ? 1.0f : 0.0f;   // exact in f32 (< 2^24)
        }
    }

    block_reduce_16(s, c, red);

    if (threadIdx.x < 2 * NGROUPS)
        g_part[blockIdx.x * 2 * NGROUPS + threadIdx.x] = red[threadIdx.x];
    __syncthreads();

    if (threadIdx.x == 0) {
        __threadfence();
        unsigned v = atomicAdd(&g_counter, 1u);
        is_last = (v == gridDim.x - 1);
    }
    __syncthreads();
    if (!is_last) return;

    // Final reduction over per-block partials (L2-hot, 888*16 floats)
    float fs[NGROUPS], fc[NGROUPS];
#pragma unroll
    for (int j = 0; j < NGROUPS; j++) { fs[j] = 0.0f; fc[j] = 0.0f; }
    for (int b = threadIdx.x; b < gridDim.x; b += THREADS) {
#pragma unroll
        for (int j = 0; j < NGROUPS; j++) {
            fs[j] += g_part[b * 2 * NGROUPS + j];
            fc[j] += g_part[b * 2 * NGROUPS + NGROUPS + j];
        }
    }
    __syncthreads();
    block_reduce_16(fs, fc, red);

    if (threadIdx.x == 0) {
        float msum = 0.0f;
#pragma unroll
        for (int j = 0; j < NGROUPS; j++) {
            float cnt = red[NGROUPS + j];
            msum += (cnt > 0.0f) ? (red[j] / cnt) : 0.0f;
        }
        out[0] = fabsf(0.5f - msum * (1.0f / NGROUPS));
        g_counter = 0;   // reset for next graph replay
    }
}

extern "C" void kernel_launch(void* const* d_in, const int* in_sizes, int n_in,
                              void* d_out, int out_size) {
    const float* in  = (const float*)d_in[0];
    const int*   tgt = (const int*)d_in[1];
    const int*   grp = (const int*)d_in[2];
    float*       out = (float*)d_out;
    int n = in_sizes[1];  // N rows

    int blocks = NBLOCKS;
    int maxb = (n + THREADS - 1) / THREADS;
    if (blocks > maxb) blocks = maxb;
    if (blocks > MAX_BLOCKS) blocks = MAX_BLOCKS;
    if (blocks < 1) blocks = 1;
    fused_kernel<<<blocks, THREADS>>>(in, tgt, grp, out, n);
}